// round 10
// baseline (speedup 1.0000x reference)
#include <cuda_runtime.h>
#include <cstdint>

#define TPB 128
// Per-sample smem stride 51 (odd => conflict-free rows). Euler of bone i at
// slots 3i..3i+2; joint i+1 written at its NATURAL slot 3(i+1) (bone i+1's
// euler prefetched one bone ahead). Root -> slots 0..2. After compute the
// buffer equals the packed output layout exactly (linear copy out).
#define EOSTR 51
#define GRID_BLOCKS 1216   // 152 SMs * 8 (2 resident waves of 4 blocks/SM)

__device__ __forceinline__ void cp_async4(float* dst_smem, const float* src_gmem) {
    unsigned int da = (unsigned int)__cvta_generic_to_shared(dst_smem);
    asm volatile("cp.async.ca.shared.global [%0], [%1], 4;\n"
                 :: "r"(da), "l"(src_gmem) : "memory");
}

__device__ __forceinline__ void euler_R(float ax, float ay, float az, float R[9]) {
    float sx, cx, sy, cy, sz, cz;
    __sincosf(ax, &sx, &cx);
    __sincosf(ay, &sy, &cy);
    __sincosf(az, &sz, &cz);
    float sxsy = sx * sy;
    float cxsy = cx * sy;
    R[0] = cy * cz;                 R[1] = -cy * sz;                 R[2] = sy;
    R[3] = fmaf(sxsy, cz, cx * sz); R[4] = fmaf(-sxsy, sz, cx * cz); R[5] = -sx * cy;
    R[6] = fmaf(-cxsy, cz, sx * sz);R[7] = fmaf(cxsy, sz, sx * cz);  R[8] = cx * cy;
}

__device__ __forceinline__ void compose(const float Mp[9], const float R[9], float Mc[9]) {
#pragma unroll
    for (int i = 0; i < 3; i++) {
#pragma unroll
        for (int j = 0; j < 3; j++) {
            Mc[i * 3 + j] = fmaf(Mp[i * 3 + 0], R[0 + j],
                            fmaf(Mp[i * 3 + 1], R[3 + j],
                                 Mp[i * 3 + 2] * R[6 + j]));
        }
    }
}

#define PREFETCH(b) nx = eo[3*(b)]; ny = eo[3*(b)+1]; nz = eo[3*(b)+2]
#define STOREJ(j, X, Y, Z) eo[3*(j)] = (X); eo[3*(j)+1] = (Y); eo[3*(j)+2] = (Z)
#define SHIFT() ax = nx; ay = ny; az = nz

__device__ __forceinline__ void fk_compute(float* eo, const float L[16]) {
    float ax = eo[0], ay = eo[1], az = eo[2];
    float nx, ny, nz;
    float R[9], MA[9], MB[9], M8[9];
    float px, py, pz, p8x, p8y, p8z;

    // leg 1: bones 0,1,2 -> joints 1,2,3 (parent = root, M = I)
    PREFETCH(1);
    euler_R(ax, ay, az, MA);
    px = L[0] * MA[6]; py = L[0] * MA[7]; pz = L[0] * MA[8];
    STOREJ(1, px, py, pz); SHIFT();

    PREFETCH(2);
    euler_R(ax, ay, az, R); compose(MA, R, MB);
    px = fmaf(L[1], MB[6], px); py = fmaf(L[1], MB[7], py); pz = fmaf(L[1], MB[8], pz);
    STOREJ(2, px, py, pz); SHIFT();

    PREFETCH(3);
    euler_R(ax, ay, az, R); compose(MB, R, MA);
    px = fmaf(L[2], MA[6], px); py = fmaf(L[2], MA[7], py); pz = fmaf(L[2], MA[8], pz);
    STOREJ(3, px, py, pz); SHIFT();

    // leg 2: bones 3,4,5 -> joints 4,5,6
    PREFETCH(4);
    euler_R(ax, ay, az, MA);
    px = L[3] * MA[6]; py = L[3] * MA[7]; pz = L[3] * MA[8];
    STOREJ(4, px, py, pz); SHIFT();

    PREFETCH(5);
    euler_R(ax, ay, az, R); compose(MA, R, MB);
    px = fmaf(L[4], MB[6], px); py = fmaf(L[4], MB[7], py); pz = fmaf(L[4], MB[8], pz);
    STOREJ(5, px, py, pz); SHIFT();

    PREFETCH(6);
    euler_R(ax, ay, az, R); compose(MB, R, MA);
    px = fmaf(L[5], MA[6], px); py = fmaf(L[5], MA[7], py); pz = fmaf(L[5], MA[8], pz);
    STOREJ(6, px, py, pz); SHIFT();

    // spine: bone 6 (0->7), bone 7 (7->8)
    PREFETCH(7);
    euler_R(ax, ay, az, MA);
    px = L[6] * MA[6]; py = L[6] * MA[7]; pz = L[6] * MA[8];
    STOREJ(7, px, py, pz); SHIFT();

    PREFETCH(8);
    euler_R(ax, ay, az, R); compose(MA, R, M8);
    p8x = fmaf(L[7], M8[6], px); p8y = fmaf(L[7], M8[7], py); p8z = fmaf(L[7], M8[8], pz);
    STOREJ(8, p8x, p8y, p8z); SHIFT();

    // head: bones 8 (8->9), 9 (9->10)
    PREFETCH(9);
    euler_R(ax, ay, az, R); compose(M8, R, MA);
    px = fmaf(L[8], MA[6], p8x); py = fmaf(L[8], MA[7], p8y); pz = fmaf(L[8], MA[8], p8z);
    STOREJ(9, px, py, pz); SHIFT();

    PREFETCH(10);
    euler_R(ax, ay, az, R); compose(MA, R, MB);
    px = fmaf(L[9], MB[6], px); py = fmaf(L[9], MB[7], py); pz = fmaf(L[9], MB[8], pz);
    STOREJ(10, px, py, pz); SHIFT();

    // arm A: bones 10,11,12 (8->11->12->13)
    PREFETCH(11);
    euler_R(ax, ay, az, R); compose(M8, R, MA);
    px = fmaf(L[10], MA[6], p8x); py = fmaf(L[10], MA[7], p8y); pz = fmaf(L[10], MA[8], p8z);
    STOREJ(11, px, py, pz); SHIFT();

    PREFETCH(12);
    euler_R(ax, ay, az, R); compose(MA, R, MB);
    px = fmaf(L[11], MB[6], px); py = fmaf(L[11], MB[7], py); pz = fmaf(L[11], MB[8], pz);
    STOREJ(12, px, py, pz); SHIFT();

    PREFETCH(13);
    euler_R(ax, ay, az, R); compose(MB, R, MA);
    px = fmaf(L[12], MA[6], px); py = fmaf(L[12], MA[7], py); pz = fmaf(L[12], MA[8], pz);
    STOREJ(13, px, py, pz); SHIFT();

    // arm B: bones 13,14,15 (8->14->15->16)
    PREFETCH(14);
    euler_R(ax, ay, az, R); compose(M8, R, MA);
    px = fmaf(L[13], MA[6], p8x); py = fmaf(L[13], MA[7], p8y); pz = fmaf(L[13], MA[8], p8z);
    STOREJ(14, px, py, pz); SHIFT();

    PREFETCH(15);
    euler_R(ax, ay, az, R); compose(MA, R, MB);
    px = fmaf(L[14], MB[6], px); py = fmaf(L[14], MB[7], py); pz = fmaf(L[14], MB[8], pz);
    STOREJ(15, px, py, pz); SHIFT();

    euler_R(ax, ay, az, R); compose(MB, R, MA);
    px = fmaf(L[15], MA[6], px); py = fmaf(L[15], MA[7], py); pz = fmaf(L[15], MA[8], pz);
    STOREJ(16, px, py, pz);

    eo[0] = 0.f; eo[1] = 0.f; eo[2] = 0.f;   // root
}

extern "C" __global__ void __launch_bounds__(TPB, 4)
fk_kernel(const float* __restrict__ euler, const float* __restrict__ blen,
          float* __restrict__ out, int N, int ntiles)
{
    extern __shared__ float sm[];   // 2 * TPB * EOSTR floats
    const int t  = threadIdx.x;
    const int nb = gridDim.x;

    // ---- issue one tile's euler floats via cp.async (coalesced GMEM,
    //      conflict-free stride-51 smem, fully asynchronous) ----
    auto issue_tile = [&](int tile, float* buf) {
        if (tile >= ntiles) return;
        const int base = tile * TPB;
        const int ns   = min(TPB, N - base);
        const int ne   = ns * 48;
        const float* ge = euler + (size_t)base * 48;
        int i = t;
        int s = t / 48;
        int r = t - s * 48;
#pragma unroll 6
        for (int j = 0; j < 48; j++) {
            if (i >= ne) break;
            cp_async4(buf + s * EOSTR + r, ge + i);
            i += TPB;
            r += 32; s += 2;                 // TPB = 2*48 + 32
            if (r >= 48) { r -= 48; s++; }
        }
    };

    // ---- load one tile's bone lengths into registers (4 LDG.128) ----
    auto load_L = [&](int tile, float* Lr) {
        if (tile >= ntiles) return;
        const int base = tile * TPB;
        const int ns   = min(TPB, N - base);
        if (t < ns) {
            const float4* gb = (const float4*)(blen + (size_t)(base + t) * 16);
            float4 a = gb[0], b = gb[1], c = gb[2], d = gb[3];
            Lr[0]=a.x;  Lr[1]=a.y;  Lr[2]=a.z;  Lr[3]=a.w;
            Lr[4]=b.x;  Lr[5]=b.y;  Lr[6]=b.z;  Lr[7]=b.w;
            Lr[8]=c.x;  Lr[9]=c.y;  Lr[10]=c.z; Lr[11]=c.w;
            Lr[12]=d.x; Lr[13]=d.y; Lr[14]=d.z; Lr[15]=d.w;
        }
    };

    float Lc[16], Ln[16];
    int k = blockIdx.x;
    if (k >= ntiles) return;
    int p = 0;

    // prologue: tile k in flight (group 0), lengths for tile k
    issue_tile(k, sm);
    asm volatile("cp.async.commit_group;\n" ::: "memory");
    load_L(k, Lc);

    for (; k < ntiles; k += nb) {
        const int knext = k + nb;

        // issue next tile into the other buffer + prefetch its lengths
        issue_tile(knext, sm + (p ^ 1) * (TPB * EOSTR));
        asm volatile("cp.async.commit_group;\n" ::: "memory");
        load_L(knext, Ln);

        // wait for current tile's euler data (allow next tile's group pending)
        asm volatile("cp.async.wait_group 1;\n" ::: "memory");
        __syncthreads();

        float* buf = sm + p * (TPB * EOSTR);
        const int base = k * TPB;
        const int ns   = min(TPB, N - base);

        if (t < ns) fk_compute(buf + t * EOSTR, Lc);
        __syncthreads();

        // store: buffer == packed output layout; pure linear copy
        float* go = out + (size_t)base * 51;
        if (ns == TPB) {
            float4* go4 = (float4*)go;
            const float4* se4 = (const float4*)buf;
#pragma unroll
            for (int q = 0; q < 12; q++)
                go4[t + q * TPB] = se4[t + q * TPB];
            if (t < 96)
                go4[t + 12 * TPB] = se4[t + 12 * TPB];
        } else {
            const int nf = ns * 51;
            for (int g = t; g < nf; g += TPB)
                go[g] = buf[g];
        }
        __syncthreads();   // buffer p reusable for tile k+2*nb next iteration

        p ^= 1;
#pragma unroll
        for (int q = 0; q < 16; q++) Lc[q] = Ln[q];
    }
}

extern "C" void kernel_launch(void* const* d_in, const int* in_sizes, int n_in,
                              void* d_out, int out_size)
{
    const float* euler = (const float*)d_in[0];   // (N,16,3) f32
    const float* blen  = (const float*)d_in[1];   // (N,16,1) f32
    float* out = (float*)d_out;                   // (N,17,3) f32

    const int N = in_sizes[0] / 48;
    const int ntiles = (N + TPB - 1) / TPB;
    const int grid = ntiles < GRID_BLOCKS ? ntiles : GRID_BLOCKS;
    const size_t smem = 2 * (size_t)TPB * EOSTR * sizeof(float); // 52,224 B

    cudaFuncSetAttribute(fk_kernel, cudaFuncAttributeMaxDynamicSharedMemorySize, (int)smem);
    cudaFuncSetAttribute(fk_kernel, cudaFuncAttributePreferredSharedMemoryCarveout,
                         cudaSharedmemCarveoutMaxShared);
    fk_kernel<<<grid, TPB, smem>>>(euler, blen, out, N, ntiles);
}

// round 11
// speedup vs baseline: 1.2150x; 1.2150x over previous
#include <cuda_runtime.h>

#define TPB 64
// Per-sample smem stride 51 (odd => conflict-free rows). Euler of bone i at
// slots 3i..3i+2; joint i+1 written at its NATURAL slot 3(i+1) (bone i+1's
// euler prefetched one bone ahead). Root -> slots 0..2. After compute the
// buffer equals the packed output layout exactly (linear float4 copy out).
#define EOSTR 51

__device__ __forceinline__ void euler_R(float ax, float ay, float az, float R[9]) {
    float sx, cx, sy, cy, sz, cz;
    __sincosf(ax, &sx, &cx);
    __sincosf(ay, &sy, &cy);
    __sincosf(az, &sz, &cz);
    float sxsy = sx * sy;
    float cxsy = cx * sy;
    R[0] = cy * cz;                 R[1] = -cy * sz;                 R[2] = sy;
    R[3] = fmaf(sxsy, cz, cx * sz); R[4] = fmaf(-sxsy, sz, cx * cz); R[5] = -sx * cy;
    R[6] = fmaf(-cxsy, cz, sx * sz);R[7] = fmaf(cxsy, sz, sx * cz);  R[8] = cx * cy;
}

__device__ __forceinline__ void compose(const float Mp[9], const float R[9], float Mc[9]) {
#pragma unroll
    for (int i = 0; i < 3; i++) {
#pragma unroll
        for (int j = 0; j < 3; j++) {
            Mc[i * 3 + j] = fmaf(Mp[i * 3 + 0], R[0 + j],
                            fmaf(Mp[i * 3 + 1], R[3 + j],
                                 Mp[i * 3 + 2] * R[6 + j]));
        }
    }
}

#define PREFETCH(b) nx = eo[3*(b)]; ny = eo[3*(b)+1]; nz = eo[3*(b)+2]
#define STOREJ(j, X, Y, Z) eo[3*(j)] = (X); eo[3*(j)+1] = (Y); eo[3*(j)+2] = (Z)
#define SHIFT() ax = nx; ay = ny; az = nz

__device__ __forceinline__ void fk_compute(float* eo, const float L[16]) {
    float ax = eo[0], ay = eo[1], az = eo[2];
    float nx, ny, nz;
    float R[9], MA[9], MB[9], M8[9];
    float px, py, pz, p8x, p8y, p8z;

    // leg 1: bones 0,1,2 -> joints 1,2,3 (parent = root, M = I)
    PREFETCH(1);
    euler_R(ax, ay, az, MA);
    px = L[0] * MA[6]; py = L[0] * MA[7]; pz = L[0] * MA[8];
    STOREJ(1, px, py, pz); SHIFT();

    PREFETCH(2);
    euler_R(ax, ay, az, R); compose(MA, R, MB);
    px = fmaf(L[1], MB[6], px); py = fmaf(L[1], MB[7], py); pz = fmaf(L[1], MB[8], pz);
    STOREJ(2, px, py, pz); SHIFT();

    PREFETCH(3);
    euler_R(ax, ay, az, R); compose(MB, R, MA);
    px = fmaf(L[2], MA[6], px); py = fmaf(L[2], MA[7], py); pz = fmaf(L[2], MA[8], pz);
    STOREJ(3, px, py, pz); SHIFT();

    // leg 2: bones 3,4,5 -> joints 4,5,6
    PREFETCH(4);
    euler_R(ax, ay, az, MA);
    px = L[3] * MA[6]; py = L[3] * MA[7]; pz = L[3] * MA[8];
    STOREJ(4, px, py, pz); SHIFT();

    PREFETCH(5);
    euler_R(ax, ay, az, R); compose(MA, R, MB);
    px = fmaf(L[4], MB[6], px); py = fmaf(L[4], MB[7], py); pz = fmaf(L[4], MB[8], pz);
    STOREJ(5, px, py, pz); SHIFT();

    PREFETCH(6);
    euler_R(ax, ay, az, R); compose(MB, R, MA);
    px = fmaf(L[5], MA[6], px); py = fmaf(L[5], MA[7], py); pz = fmaf(L[5], MA[8], pz);
    STOREJ(6, px, py, pz); SHIFT();

    // spine: bone 6 (0->7), bone 7 (7->8)
    PREFETCH(7);
    euler_R(ax, ay, az, MA);
    px = L[6] * MA[6]; py = L[6] * MA[7]; pz = L[6] * MA[8];
    STOREJ(7, px, py, pz); SHIFT();

    PREFETCH(8);
    euler_R(ax, ay, az, R); compose(MA, R, M8);
    p8x = fmaf(L[7], M8[6], px); p8y = fmaf(L[7], M8[7], py); p8z = fmaf(L[7], M8[8], pz);
    STOREJ(8, p8x, p8y, p8z); SHIFT();

    // head: bones 8 (8->9), 9 (9->10)
    PREFETCH(9);
    euler_R(ax, ay, az, R); compose(M8, R, MA);
    px = fmaf(L[8], MA[6], p8x); py = fmaf(L[8], MA[7], p8y); pz = fmaf(L[8], MA[8], p8z);
    STOREJ(9, px, py, pz); SHIFT();

    PREFETCH(10);
    euler_R(ax, ay, az, R); compose(MA, R, MB);
    px = fmaf(L[9], MB[6], px); py = fmaf(L[9], MB[7], py); pz = fmaf(L[9], MB[8], pz);
    STOREJ(10, px, py, pz); SHIFT();

    // arm A: bones 10,11,12 (8->11->12->13)
    PREFETCH(11);
    euler_R(ax, ay, az, R); compose(M8, R, MA);
    px = fmaf(L[10], MA[6], p8x); py = fmaf(L[10], MA[7], p8y); pz = fmaf(L[10], MA[8], p8z);
    STOREJ(11, px, py, pz); SHIFT();

    PREFETCH(12);
    euler_R(ax, ay, az, R); compose(MA, R, MB);
    px = fmaf(L[11], MB[6], px); py = fmaf(L[11], MB[7], py); pz = fmaf(L[11], MB[8], pz);
    STOREJ(12, px, py, pz); SHIFT();

    PREFETCH(13);
    euler_R(ax, ay, az, R); compose(MB, R, MA);
    px = fmaf(L[12], MA[6], px); py = fmaf(L[12], MA[7], py); pz = fmaf(L[12], MA[8], pz);
    STOREJ(13, px, py, pz); SHIFT();

    // arm B: bones 13,14,15 (8->14->15->16)
    PREFETCH(14);
    euler_R(ax, ay, az, R); compose(M8, R, MA);
    px = fmaf(L[13], MA[6], p8x); py = fmaf(L[13], MA[7], p8y); pz = fmaf(L[13], MA[8], p8z);
    STOREJ(14, px, py, pz); SHIFT();

    PREFETCH(15);
    euler_R(ax, ay, az, R); compose(MA, R, MB);
    px = fmaf(L[14], MB[6], px); py = fmaf(L[14], MB[7], py); pz = fmaf(L[14], MB[8], pz);
    STOREJ(15, px, py, pz); SHIFT();

    euler_R(ax, ay, az, R); compose(MB, R, MA);
    px = fmaf(L[15], MA[6], px); py = fmaf(L[15], MA[7], py); pz = fmaf(L[15], MA[8], pz);
    STOREJ(16, px, py, pz);

    eo[0] = 0.f; eo[1] = 0.f; eo[2] = 0.f;   // root
}

extern "C" __global__ void __launch_bounds__(TPB, 16)
fk_kernel(const float* __restrict__ euler, const float* __restrict__ blen,
          float* __restrict__ out, int N)
{
    extern __shared__ float sm[];
    float* s_eo = sm;                      // TPB * EOSTR

    const int t    = threadIdx.x;
    const int base = blockIdx.x * TPB;
    const int ns   = min(TPB, N - base);
    const bool full = (ns == TPB);

    // ---- euler staging: float4 LDG (12 independent loads -> high MLP),
    //      phased STS into conflict-free odd-stride rows ----
    {
        const float4* ge = (const float4*)(euler + (size_t)base * 48);
        if (full) {
#pragma unroll
            for (int k = 0; k < 12; k++) {
                int i = t + k * TPB;
                float4 v = ge[i];
                int s = i / 12, r = i - s * 12;
                float* p = s_eo + s * EOSTR + r * 4;
                p[0] = v.x; p[1] = v.y; p[2] = v.z; p[3] = v.w;
            }
        } else {
            const int ne4 = ns * 12;
            for (int i = t; i < ne4; i += TPB) {
                float4 v = ge[i];
                int s = i / 12, r = i - s * 12;
                float* p = s_eo + s * EOSTR + r * 4;
                p[0] = v.x; p[1] = v.y; p[2] = v.z; p[3] = v.w;
            }
        }
    }

    // ---- bone lengths: direct per-thread float4 LDG (adds MLP, no smem) ----
    float L[16];
    if (t < ns) {
        const float4* gb = (const float4*)(blen + (size_t)(base + t) * 16);
        float4 a = gb[0], b = gb[1], c = gb[2], d = gb[3];
        L[0]=a.x;  L[1]=a.y;  L[2]=a.z;  L[3]=a.w;
        L[4]=b.x;  L[5]=b.y;  L[6]=b.z;  L[7]=b.w;
        L[8]=c.x;  L[9]=c.y;  L[10]=c.z; L[11]=c.w;
        L[12]=d.x; L[13]=d.y; L[14]=d.z; L[15]=d.w;
    }
    __syncthreads();

    // ---- per-sample FK: outputs land at natural slots -> smem == out layout ----
    if (t < ns) {
        fk_compute(s_eo + t * EOSTR, L);
    }
    __syncthreads();

    // ---- store: pure linear copy, float4, zero index math ----
    {
        float* go = out + (size_t)base * 51;
        if (full) {
            // 51*64 = 3264 floats = 816 float4 = 12*64 + 48
            float4* go4 = (float4*)go;
            const float4* se4 = (const float4*)s_eo;
#pragma unroll
            for (int k = 0; k < 12; k++)
                go4[t + k * TPB] = se4[t + k * TPB];
            if (t < 48)
                go4[t + 12 * TPB] = se4[t + 12 * TPB];
        } else {
            const int nf = ns * 51;
            for (int g = t; g < nf; g += TPB)
                go[g] = s_eo[g];
        }
    }
}

extern "C" void kernel_launch(void* const* d_in, const int* in_sizes, int n_in,
                              void* d_out, int out_size)
{
    const float* euler = (const float*)d_in[0];   // (N,16,3) f32
    const float* blen  = (const float*)d_in[1];   // (N,16,1) f32
    float* out = (float*)d_out;                   // (N,17,3) f32

    const int N = in_sizes[0] / 48;
    const int grid = (N + TPB - 1) / TPB;
    const size_t smem = (size_t)TPB * EOSTR * sizeof(float); // 13,056 B -> 16 blocks/SM

    cudaFuncSetAttribute(fk_kernel, cudaFuncAttributeMaxDynamicSharedMemorySize, (int)smem);
    cudaFuncSetAttribute(fk_kernel, cudaFuncAttributePreferredSharedMemoryCarveout,
                         cudaSharedmemCarveoutMaxShared);
    fk_kernel<<<grid, TPB, smem>>>(euler, blen, out, N);
}